// round 12
// baseline (speedup 1.0000x reference)
#include <cuda_runtime.h>
#include <cuda_fp16.h>

#define Dh 128
#define NHEAD 16
#define NB 2
#define SEQ 2048
#define NHD (NHEAD*Dh)
#define MROWS (NB*SEQ)

__device__ __half g_Qh[(size_t)NB*NHEAD*SEQ*Dh];
__device__ __half g_Kh[(size_t)NB*NHEAD*SEQ*Dh];
__device__ __half g_VTh[(size_t)NB*NHEAD*SEQ*Dh];
__device__ float  g_CTX[(size_t)NB*NHEAD*SEQ*Dh];   // tf32-pre-rounded
__device__ float  g_Wdr[(size_t)Dh*NHD];            // Wd tf32-pre-rounded
__device__ float  g_LINV[(size_t)NB*NHEAD*SEQ];
__device__ unsigned g_MBITS[(size_t)NB*SEQ*(SEQ/32)];

#define LDA 132
#define LQW 68
#define LVW 36
#define OFF_KB0 4352
#define OFF_KB1 (4352 + 4352)
#define OFF_VB0 (4352 + 2*4352)
#define OFF_VB1 (4352 + 2*4352 + 4608)
#define SMEM_ATTN ((4352 + 2*4352 + 2*4608) * 4)

#define OA0 0
#define OA1 4224
#define OB0 8448
#define OB1 25344
#define SMEM_S3 (42240 * 4)

#define QSCALE 0.12751744532f

__device__ __forceinline__ unsigned f2tf32(float f){
    unsigned r; asm("cvt.rna.tf32.f32 %0, %1;" : "=r"(r) : "f"(f)); return r;
}
__device__ __forceinline__ float ex2f(float x){
    float r; asm("ex2.approx.f32 %0, %1;" : "=f"(r) : "f"(x)); return r;
}
__device__ __forceinline__ unsigned pack_h2(float a, float b){
    unsigned r; asm("cvt.rn.f16x2.f32 %0, %2, %1;" : "=r"(r) : "f"(a), "f"(b)); return r;
}
__device__ __forceinline__ void mma8(float* d, const unsigned* a, unsigned b0, unsigned b1){
    asm volatile("mma.sync.aligned.m16n8k8.row.col.f32.tf32.tf32.f32 "
        "{%0,%1,%2,%3},{%4,%5,%6,%7},{%8,%9},{%0,%1,%2,%3};"
        : "+f"(d[0]), "+f"(d[1]), "+f"(d[2]), "+f"(d[3])
        : "r"(a[0]), "r"(a[1]), "r"(a[2]), "r"(a[3]), "r"(b0), "r"(b1));
}
__device__ __forceinline__ void mma16h(float* d, const unsigned* a, unsigned b0, unsigned b1){
    asm volatile("mma.sync.aligned.m16n8k16.row.col.f32.f16.f16.f32 "
        "{%0,%1,%2,%3},{%4,%5,%6,%7},{%8,%9},{%0,%1,%2,%3};"
        : "+f"(d[0]), "+f"(d[1]), "+f"(d[2]), "+f"(d[3])
        : "r"(a[0]), "r"(a[1]), "r"(a[2]), "r"(a[3]), "r"(b0), "r"(b1));
}
__device__ __forceinline__ unsigned smem_u32(const void* p){
    unsigned a;
    asm("{ .reg .u64 t; cvta.to.shared.u64 t, %1; cvt.u32.u64 %0, t; }" : "=r"(a) : "l"(p));
    return a;
}
__device__ __forceinline__ void cpa16(unsigned s, const void* g){
    asm volatile("cp.async.ca.shared.global [%0], [%1], 16;" :: "r"(s), "l"(g));
}

template<int NT, int ROWS>
__device__ __forceinline__ void load_tile(unsigned* dst, const float* src, int srcStride,
                                          int tid){
    #pragma unroll
    for (int it = 0; it < ROWS*32/NT; ++it){
        int idx = tid + it*NT;
        int r = idx >> 5, c = (idx & 31) << 2;
        float4 v = *(const float4*)(src + (size_t)r*srcStride + c);
        uint4 u = make_uint4(f2tf32(v.x), f2tf32(v.y), f2tf32(v.z), f2tf32(v.w));
        *(uint4*)(dst + r*LDA + c) = u;
    }
}

// ---------------- stage 1 ----------------
__global__ __launch_bounds__(256) void stage1(
    const float* __restrict__ X, const int* __restrict__ mask,
    const float* __restrict__ Wq, const float* __restrict__ bq,
    const float* __restrict__ Wk, const float* __restrict__ bk,
    const float* __restrict__ Wv, const float* __restrict__ bv,
    const float* __restrict__ Wd)
{
    const int tid = threadIdx.x;
    const int which = blockIdx.z;

    if (which == 3){
        size_t p = (size_t)blockIdx.y * 16 + blockIdx.x;   // 0..511
        #pragma unroll
        for (int k = 0; k < 2; ++k){
            size_t o = p*512 + tid*2 + k;
            const int* src = mask + o*32;
            unsigned bits = 0;
            #pragma unroll
            for (int i = 0; i < 32; i += 4){
                int4 v = *(const int4*)(src + i);
                bits |= ((unsigned)(v.x & 1) << i)     | ((unsigned)(v.y & 1) << (i+1))
                      | ((unsigned)(v.z & 1) << (i+2)) | ((unsigned)(v.w & 1) << (i+3));
            }
            g_MBITS[o] = bits;
        }
        // Wd -> tf32-rounded copy: 262144 floats; 512 floats/block = 128 float4
        {
            size_t base = p * 512;
            if (tid < 128){
                float4 v = *(const float4*)(Wd + base + tid*4);
                uint4 u = make_uint4(f2tf32(v.x), f2tf32(v.y), f2tf32(v.z), f2tf32(v.w));
                *(uint4*)(g_Wdr + base + tid*4) = u;
            }
        }
        return;
    }

    extern __shared__ unsigned sm[];
    unsigned* As = sm;
    unsigned* Bs = sm + 128*LDA;
    const int lane = tid & 31, g = lane >> 2, t4 = lane & 3, w = tid >> 5;
    const int m0w = (w & 3) * 32, n0w = (w >> 2) * 64;
    const int m0 = blockIdx.y * 128, n0 = blockIdx.x * 128;

    const float* W    = (which == 0) ? Wq : (which == 1) ? Wk : Wv;
    const float* bias = (which == 0) ? bq : (which == 1) ? bk : bv;

    load_tile<256,128>(As, X + (size_t)m0*Dh, Dh, tid);
    load_tile<256,128>(Bs, W + (size_t)n0*Dh, Dh, tid);
    __syncthreads();

    float acc[2][8][4] = {};
    #pragma unroll 4
    for (int kk = 0; kk < 16; ++kk){
        unsigned a[2][4];
        #pragma unroll
        for (int mi = 0; mi < 2; ++mi){
            const unsigned* p = As + (m0w + mi*16 + g)*LDA + kk*8 + t4;
            a[mi][0] = p[0];       a[mi][2] = p[4];
            a[mi][1] = p[8*LDA];   a[mi][3] = p[8*LDA + 4];
        }
        #pragma unroll
        for (int j = 0; j < 8; ++j){
            const unsigned* p = Bs + (n0w + j*8 + g)*LDA + kk*8 + t4;
            mma8(acc[0][j], a[0], p[0], p[4]);
            mma8(acc[1][j], a[1], p[0], p[4]);
        }
    }

    const int b = m0 >> 11, sbase = m0 & 2047, h = n0 >> 7;
    const size_t bh = (size_t)(b*NHEAD + h);
    #pragma unroll
    for (int mi = 0; mi < 2; ++mi)
        #pragma unroll
        for (int half_ = 0; half_ < 2; ++half_){
            int rl = m0w + mi*16 + half_*8 + g;
            int s = sbase + rl;
            #pragma unroll
            for (int j = 0; j < 8; ++j){
                int d = n0w + j*8 + 2*t4;
                float v0 = acc[mi][j][half_*2]   + bias[n0 + d];
                float v1 = acc[mi][j][half_*2+1] + bias[n0 + d + 1];
                if (which == 0){
                    *(unsigned*)(g_Qh + (bh*SEQ + s)*Dh + d) = pack_h2(v0*QSCALE, v1*QSCALE);
                } else if (which == 1){
                    *(unsigned*)(g_Kh + (bh*SEQ + s)*Dh + d) = pack_h2(v0, v1);
                } else {
                    g_VTh[(bh*Dh + d)*SEQ + s]     = __float2half_rn(v0);
                    g_VTh[(bh*Dh + d + 1)*SEQ + s] = __float2half_rn(v1);
                }
            }
        }
}

// ---------------- fused attention ----------------
__global__ __launch_bounds__(128, 2) void attn_mma(float* __restrict__ weights)
{
    extern __shared__ unsigned sm[];
    unsigned* Qs = sm;
    __shared__ float lpart[64][2];
    __shared__ float linvs[64];

    const int tid = threadIdx.x, lane = tid & 31, g = lane >> 2, t4 = lane & 3, w = tid >> 5;
    const int m0w = (w & 1) * 32;
    const int wn  = w >> 1;
    const int n0s = wn * 32;
    const int n0d = wn * 64;
    const int h = blockIdx.x, q0 = blockIdx.y * 64, b = blockIdx.z;
    const size_t bh = (size_t)(b*NHEAD + h);
    const __half* Qg  = g_Qh  + bh*SEQ*Dh + (size_t)q0*Dh;
    const __half* Kg  = g_Kh  + bh*SEQ*Dh;
    const __half* VTg = g_VTh + bh*SEQ*Dh;
    const unsigned* mbits = g_MBITS + (size_t)b*SEQ*(SEQ/32);
    float* wb = weights + bh*(size_t)SEQ*SEQ;

    const unsigned smb = smem_u32(sm);
    const unsigned kb_u[2] = { smb + OFF_KB0*4u, smb + OFF_KB1*4u };
    const unsigned vb_u[2] = { smb + OFF_VB0*4u, smb + OFF_VB1*4u };

    #pragma unroll
    for (int i = 0; i < 8; ++i){
        int idx = tid + i*128;
        int r = idx >> 4, c = idx & 15;
        cpa16(smb + (unsigned)(r*LQW + c*4)*4u, Qg + (size_t)r*Dh + c*8);
        cpa16(kb_u[0] + (unsigned)(r*LQW + c*4)*4u, Kg + (size_t)r*Dh + c*8);
        int rv = idx >> 3, cv = idx & 7;
        cpa16(vb_u[0] + (unsigned)(rv*LVW + cv*4)*4u, VTg + (size_t)rv*SEQ + cv*8);
    }
    asm volatile("cp.async.commit_group;");

    float lsum[2][2] = {{0.f,0.f},{0.f,0.f}};
    float ctx[2][8][4] = {};

    for (int it = 0; it < 32; ++it){
        const int t0 = it * 64;
        const int cur = it & 1, nxt = cur ^ 1;
        if (it + 1 < 32){
            const __half* Kn  = Kg  + (size_t)(t0 + 64)*Dh;
            const __half* VTn = VTg + (t0 + 64);
            #pragma unroll
            for (int i = 0; i < 8; ++i){
                int idx = tid + i*128;
                int r = idx >> 4, c = idx & 15;
                cpa16(kb_u[nxt] + (unsigned)(r*LQW + c*4)*4u, Kn + (size_t)r*Dh + c*8);
                int rv = idx >> 3, cv = idx & 7;
                cpa16(vb_u[nxt] + (unsigned)(rv*LVW + cv*4)*4u, VTn + (size_t)rv*SEQ + cv*8);
            }
            asm volatile("cp.async.commit_group;");
            asm volatile("cp.async.wait_group 1;");
        } else {
            asm volatile("cp.async.wait_group 0;");
        }
        __syncthreads();

        const unsigned* Ks = sm + (cur ? OFF_KB1 : OFF_KB0);
        const unsigned* Vs = sm + (cur ? OFF_VB1 : OFF_VB0);
        unsigned*       Ws = sm + (cur ? OFF_KB1 : OFF_KB0);

        float acc[2][4][4] = {};
        #pragma unroll
        for (int kk = 0; kk < 8; ++kk){
            unsigned a[2][4];
            #pragma unroll
            for (int mi = 0; mi < 2; ++mi){
                const unsigned* p = Qs + (m0w + mi*16 + g)*LQW + kk*8 + t4;
                a[mi][0] = p[0];       a[mi][2] = p[4];
                a[mi][1] = p[8*LQW];   a[mi][3] = p[8*LQW + 4];
            }
            #pragma unroll
            for (int j = 0; j < 4; ++j){
                const unsigned* p = Ks + (n0s + j*8 + g)*LQW + kk*8 + t4;
                mma16h(acc[0][j], a[0], p[0], p[4]);
                mma16h(acc[1][j], a[1], p[0], p[4]);
            }
        }
        __syncthreads();

        #pragma unroll
        for (int mi = 0; mi < 2; ++mi){
            const int rl0 = m0w + mi*16 + g;
            const int r0  = q0 + rl0;
            const int wword = (t0 + n0s) >> 5;
            const unsigned mb0 = mbits[(size_t)r0*(SEQ/32) + wword];
            const unsigned mb1 = mbits[(size_t)(r0+8)*(SEQ/32) + wword];
            float* wr0 = wb + (size_t)r0*SEQ + t0;
            float* wr1 = wr0 + 8*SEQ;
            #pragma unroll
            for (int j = 0; j < 4; ++j){
                int cc = n0s + j*8 + 2*t4;
                int sh = j*8 + 2*t4;
                float u00 = ((mb0 >> sh) & 1u)     ? 0.f : ex2f(acc[mi][j][0]);
                float u01 = ((mb0 >> (sh+1)) & 1u) ? 0.f : ex2f(acc[mi][j][1]);
                float u10 = ((mb1 >> sh) & 1u)     ? 0.f : ex2f(acc[mi][j][2]);
                float u11 = ((mb1 >> (sh+1)) & 1u) ? 0.f : ex2f(acc[mi][j][3]);
                *(float2*)(wr0 + cc) = make_float2(u00, u01);
                *(float2*)(wr1 + cc) = make_float2(u10, u11);
                lsum[mi][0] += u00 + u01;
                lsum[mi][1] += u10 + u11;
                Ws[rl0*LVW + (n0s >> 1) + 4*j + t4]       = pack_h2(u00, u01);
                Ws[(rl0 + 8)*LVW + (n0s >> 1) + 4*j + t4] = pack_h2(u10, u11);
            }
        }
        __syncthreads();

        #pragma unroll
        for (int kk = 0; kk < 4; ++kk){
            unsigned a[2][4];
            #pragma unroll
            for (int mi = 0; mi < 2; ++mi){
                const unsigned* p = Ws + (m0w + mi*16 + g)*LVW + kk*8 + t4;
                a[mi][0] = p[0];       a[mi][2] = p[4];
                a[mi][1] = p[8*LVW];   a[mi][3] = p[8*LVW + 4];
            }
            #pragma unroll
            for (int j = 0; j < 8; ++j){
                const unsigned* p = Vs + (n0d + j*8 + g)*LVW + kk*8 + t4;
                mma16h(ctx[0][j], a[0], p[0], p[4]);
                mma16h(ctx[1][j], a[1], p[0], p[4]);
            }
        }
        __syncthreads();
    }

    #pragma unroll
    for (int mi = 0; mi < 2; ++mi)
        #pragma unroll
        for (int half_ = 0; half_ < 2; ++half_){
            float v = lsum[mi][half_];
            v += __shfl_xor_sync(0xffffffffu, v, 1);
            v += __shfl_xor_sync(0xffffffffu, v, 2);
            if (t4 == 0) lpart[m0w + mi*16 + half_*8 + g][wn] = v;
        }
    __syncthreads();
    if (tid < 64){
        float li = 1.0f / (lpart[tid][0] + lpart[tid][1]);
        linvs[tid] = li;
        g_LINV[bh*SEQ + q0 + tid] = li;
    }
    __syncthreads();

    float* Cb = g_CTX + (bh*SEQ + (size_t)q0)*Dh;
    #pragma unroll
    for (int mi = 0; mi < 2; ++mi)
        #pragma unroll
        for (int half_ = 0; half_ < 2; ++half_){
            int rl = m0w + mi*16 + half_*8 + g;
            float li = linvs[rl];
            #pragma unroll
            for (int j = 0; j < 8; ++j){
                int d = n0d + j*8 + 2*t4;
                float c0 = __uint_as_float(f2tf32(ctx[mi][j][half_*2]*li));
                float c1 = __uint_as_float(f2tf32(ctx[mi][j][half_*2+1]*li));
                *(float2*)(Cb + (size_t)rl*Dh + d) = make_float2(c0, c1);
            }
        }
}

// ---------------- stage 3: outproj (blocks 0..127) + normalize (rest) ----------------
__global__ __launch_bounds__(256) void stage3(const float* __restrict__ bd,
                                              float* __restrict__ out,
                                              float* __restrict__ weights)
{
    const int tid = threadIdx.x;
    const int bid = blockIdx.x;

    if (bid >= 128){
        const int row0 = (bid - 128) * 16;
        float4* w4 = (float4*)(weights + (size_t)row0 * SEQ);
        #pragma unroll 8
        for (int i = tid; i < 16*512; i += 256){
            int r = i >> 9;
            float li = g_LINV[row0 + r];
            float4 v = w4[i];
            v.x *= li; v.y *= li; v.z *= li; v.w *= li;
            w4[i] = v;
        }
        return;
    }

    extern __shared__ unsigned sm[];
    const unsigned smb = smem_u32(sm);
    const int lane = tid & 31, g = lane >> 2, t4 = lane & 3, w = tid >> 5;
    const int m0w = (w & 1) * 16, n0w = (w >> 1) * 32;
    const int m0 = bid * 32;
    const int b = m0 >> 11, sbase = m0 & 2047;

    const unsigned oa[2] = { smb + OA0*4u, smb + OA1*4u };
    const unsigned ob[2] = { smb + OB0*4u, smb + OB1*4u };

    {
        const float* Ag = g_CTX + (((size_t)(b*NHEAD))*SEQ + sbase)*Dh;
        #pragma unroll
        for (int i = 0; i < 4; ++i){
            int idx = tid + i*256;
            int r = idx >> 5, c = (idx & 31) << 2;
            cpa16(oa[0] + (unsigned)(r*LDA + c)*4u, Ag + (size_t)r*Dh + c);
        }
        #pragma unroll
        for (int i = 0; i < 16; ++i){
            int idx = tid + i*256;
            int r = idx >> 5, c = (idx & 31) << 2;
            cpa16(ob[0] + (unsigned)(r*LDA + c)*4u, g_Wdr + (size_t)r*NHD + c);
        }
        asm volatile("cp.async.commit_group;");
    }

    float acc[4][4] = {};
    for (int kt = 0; kt < 16; ++kt){
        const int cur = kt & 1, nxt = cur ^ 1;
        if (kt + 1 < 16){
            const float* Ag = g_CTX + (((size_t)(b*NHEAD + kt + 1))*SEQ + sbase)*Dh;
            const float* Bg = g_Wdr + (kt + 1)*Dh;
            #pragma unroll
            for (int i = 0; i < 4; ++i){
                int idx = tid + i*256;
                int r = idx >> 5, c = (idx & 31) << 2;
                cpa16(oa[nxt] + (unsigned)(r*LDA + c)*4u, Ag + (size_t)r*Dh + c);
            }
            #pragma unroll
            for (int i = 0; i < 16; ++i){
                int idx = tid + i*256;
                int r = idx >> 5, c = (idx & 31) << 2;
                cpa16(ob[nxt] + (unsigned)(r*LDA + c)*4u, Bg + (size_t)r*NHD + c);
            }
            asm volatile("cp.async.commit_group;");
            asm volatile("cp.async.wait_group 1;");
        } else {
            asm volatile("cp.async.wait_group 0;");
        }
        __syncthreads();

        const unsigned* As = sm + (cur ? OA1 : OA0);
        const unsigned* Bs = sm + (cur ? OB1 : OB0);

        #pragma unroll 4
        for (int kk = 0; kk < 16; ++kk){
            unsigned a[4];
            const unsigned* pa = As + (m0w + g)*LDA + kk*8 + t4;
            a[0] = pa[0];       a[2] = pa[4];
            a[1] = pa[8*LDA];   a[3] = pa[8*LDA + 4];
            #pragma unroll
            for (int j = 0; j < 4; ++j){
                const unsigned* p = Bs + (n0w + j*8 + g)*LDA + kk*8 + t4;
                mma8(acc[j], a, p[0], p[4]);
            }
        }
        __syncthreads();
    }

    #pragma unroll
    for (int half_ = 0; half_ < 2; ++half_){
        int rl = m0w + half_*8 + g;
        float* Or = out + (size_t)(m0 + rl)*Dh;
        #pragma unroll
        for (int j = 0; j < 4; ++j){
            int d = n0w + j*8 + 2*t4;
            *(float2*)(Or + d) = make_float2(acc[j][half_*2]   + bd[d],
                                             acc[j][half_*2+1] + bd[d + 1]);
        }
    }
}

// ---------------------------------------------------------------------------
extern "C" void kernel_launch(void* const* d_in, const int* in_sizes, int n_in,
                              void* d_out, int out_size)
{
    (void)in_sizes; (void)n_in; (void)out_size;
    const float* x    = (const float*)d_in[0];
    const int*   mask = (const int*)  d_in[1];
    const float* Wq   = (const float*)d_in[2];
    const float* bq   = (const float*)d_in[3];
    const float* Wk   = (const float*)d_in[4];
    const float* bk   = (const float*)d_in[5];
    const float* Wv   = (const float*)d_in[6];
    const float* bv   = (const float*)d_in[7];
    const float* Wd   = (const float*)d_in[8];
    const float* bd   = (const float*)d_in[9];

    float* out     = (float*)d_out;
    float* weights = out + (size_t)NB*SEQ*Dh;

    const size_t smem_proj = (size_t)2*128*LDA*4;
    const size_t smem_attn = SMEM_ATTN;
    const size_t smem_s3   = SMEM_S3;

    cudaFuncSetAttribute(stage1,   cudaFuncAttributeMaxDynamicSharedMemorySize, (int)smem_proj);
    cudaFuncSetAttribute(attn_mma, cudaFuncAttributeMaxDynamicSharedMemorySize, (int)smem_attn);
    cudaFuncSetAttribute(stage3,   cudaFuncAttributeMaxDynamicSharedMemorySize, (int)smem_s3);

    dim3 g1(NHD/128, MROWS/128, 4);
    stage1<<<g1, 256, smem_proj>>>(x, mask, Wq, bq, Wk, bk, Wv, bv, Wd);

    dim3 g2(NHEAD, SEQ/64, NB);
    attn_mma<<<g2, 128, smem_attn>>>(weights);

    stage3<<<128 + MROWS*NHEAD/16, 256, smem_s3>>>(bd, out, weights);
}

// round 13
// speedup vs baseline: 1.1441x; 1.1441x over previous
#include <cuda_runtime.h>
#include <cuda_fp16.h>

#define Dh 128
#define NHEAD 16
#define NB 2
#define SEQ 2048
#define NHD (NHEAD*Dh)
#define MROWS (NB*SEQ)

__device__ __half g_Qh[(size_t)NB*NHEAD*SEQ*Dh];
__device__ __half g_Kh[(size_t)NB*NHEAD*SEQ*Dh];
__device__ __half g_VTh[(size_t)NB*NHEAD*SEQ*Dh];
__device__ float  g_CTX[(size_t)NB*NHEAD*SEQ*Dh];   // tf32-pre-rounded
__device__ float  g_Wdr[(size_t)Dh*NHD];            // Wd tf32-pre-rounded
__device__ float  g_LINV[(size_t)NB*NHEAD*SEQ];
__device__ unsigned g_MBITS[(size_t)NB*SEQ*(SEQ/32)];

#define LDA 132
#define LQW 68
#define LVW 36
#define OFF_KB0 4352
#define OFF_KB1 (4352 + 4352)
#define OFF_VB0 (4352 + 2*4352)
#define OFF_VB1 (4352 + 2*4352 + 4608)
#define SMEM_ATTN ((4352 + 2*4352 + 2*4608) * 4)

#define OA0 0
#define OA1 4224
#define OB0 8448
#define OB1 25344
#define SMEM_OP (42240 * 4)     // 168960 B

#define QSCALE 0.12751744532f

__device__ __forceinline__ unsigned f2tf32(float f){
    unsigned r; asm("cvt.rna.tf32.f32 %0, %1;" : "=r"(r) : "f"(f)); return r;
}
__device__ __forceinline__ float ex2f(float x){
    float r; asm("ex2.approx.f32 %0, %1;" : "=f"(r) : "f"(x)); return r;
}
__device__ __forceinline__ unsigned pack_h2(float a, float b){
    unsigned r; asm("cvt.rn.f16x2.f32 %0, %2, %1;" : "=r"(r) : "f"(a), "f"(b)); return r;
}
__device__ __forceinline__ void mma8(float* d, const unsigned* a, unsigned b0, unsigned b1){
    asm volatile("mma.sync.aligned.m16n8k8.row.col.f32.tf32.tf32.f32 "
        "{%0,%1,%2,%3},{%4,%5,%6,%7},{%8,%9},{%0,%1,%2,%3};"
        : "+f"(d[0]), "+f"(d[1]), "+f"(d[2]), "+f"(d[3])
        : "r"(a[0]), "r"(a[1]), "r"(a[2]), "r"(a[3]), "r"(b0), "r"(b1));
}
__device__ __forceinline__ void mma16h(float* d, const unsigned* a, unsigned b0, unsigned b1){
    asm volatile("mma.sync.aligned.m16n8k16.row.col.f32.f16.f16.f32 "
        "{%0,%1,%2,%3},{%4,%5,%6,%7},{%8,%9},{%0,%1,%2,%3};"
        : "+f"(d[0]), "+f"(d[1]), "+f"(d[2]), "+f"(d[3])
        : "r"(a[0]), "r"(a[1]), "r"(a[2]), "r"(a[3]), "r"(b0), "r"(b1));
}
__device__ __forceinline__ unsigned smem_u32(const void* p){
    unsigned a;
    asm("{ .reg .u64 t; cvta.to.shared.u64 t, %1; cvt.u32.u64 %0, t; }" : "=r"(a) : "l"(p));
    return a;
}
__device__ __forceinline__ void cpa16(unsigned s, const void* g){
    asm volatile("cp.async.ca.shared.global [%0], [%1], 16;" :: "r"(s), "l"(g));
}

template<int NT, int ROWS>
__device__ __forceinline__ void load_tile(unsigned* dst, const float* src, int srcStride,
                                          int tid){
    #pragma unroll
    for (int it = 0; it < ROWS*32/NT; ++it){
        int idx = tid + it*NT;
        int r = idx >> 5, c = (idx & 31) << 2;
        float4 v = *(const float4*)(src + (size_t)r*srcStride + c);
        uint4 u = make_uint4(f2tf32(v.x), f2tf32(v.y), f2tf32(v.z), f2tf32(v.w));
        *(uint4*)(dst + r*LDA + c) = u;
    }
}

// ---------------- stage 1: QKV proj (z=0..2) + mask bitpack / Wd round (z=3) ----------
__global__ __launch_bounds__(256) void stage1(
    const float* __restrict__ X, const int* __restrict__ mask,
    const float* __restrict__ Wq, const float* __restrict__ bq,
    const float* __restrict__ Wk, const float* __restrict__ bk,
    const float* __restrict__ Wv, const float* __restrict__ bv,
    const float* __restrict__ Wd)
{
    const int tid = threadIdx.x;
    const int which = blockIdx.z;

    if (which == 3){
        size_t p = (size_t)blockIdx.y * 16 + blockIdx.x;   // 0..511
        #pragma unroll
        for (int k = 0; k < 2; ++k){
            size_t o = p*512 + tid*2 + k;
            const int* src = mask + o*32;
            unsigned bits = 0;
            #pragma unroll
            for (int i = 0; i < 32; i += 4){
                int4 v = *(const int4*)(src + i);
                bits |= ((unsigned)(v.x & 1) << i)     | ((unsigned)(v.y & 1) << (i+1))
                      | ((unsigned)(v.z & 1) << (i+2)) | ((unsigned)(v.w & 1) << (i+3));
            }
            g_MBITS[o] = bits;
        }
        {
            size_t base = p * 512;
            if (tid < 128){
                float4 v = *(const float4*)(Wd + base + tid*4);
                uint4 u = make_uint4(f2tf32(v.x), f2tf32(v.y), f2tf32(v.z), f2tf32(v.w));
                *(uint4*)(g_Wdr + base + tid*4) = u;
            }
        }
        return;
    }

    extern __shared__ unsigned sm[];
    unsigned* As = sm;
    unsigned* Bs = sm + 128*LDA;
    const int lane = tid & 31, g = lane >> 2, t4 = lane & 3, w = tid >> 5;
    const int m0w = (w & 3) * 32, n0w = (w >> 2) * 64;
    const int m0 = blockIdx.y * 128, n0 = blockIdx.x * 128;

    const float* W    = (which == 0) ? Wq : (which == 1) ? Wk : Wv;
    const float* bias = (which == 0) ? bq : (which == 1) ? bk : bv;

    load_tile<256,128>(As, X + (size_t)m0*Dh, Dh, tid);
    load_tile<256,128>(Bs, W + (size_t)n0*Dh, Dh, tid);
    __syncthreads();

    float acc[2][8][4] = {};
    #pragma unroll 4
    for (int kk = 0; kk < 16; ++kk){
        unsigned a[2][4];
        #pragma unroll
        for (int mi = 0; mi < 2; ++mi){
            const unsigned* p = As + (m0w + mi*16 + g)*LDA + kk*8 + t4;
            a[mi][0] = p[0];       a[mi][2] = p[4];
            a[mi][1] = p[8*LDA];   a[mi][3] = p[8*LDA + 4];
        }
        #pragma unroll
        for (int j = 0; j < 8; ++j){
            const unsigned* p = Bs + (n0w + j*8 + g)*LDA + kk*8 + t4;
            mma8(acc[0][j], a[0], p[0], p[4]);
            mma8(acc[1][j], a[1], p[0], p[4]);
        }
    }

    const int b = m0 >> 11, sbase = m0 & 2047, h = n0 >> 7;
    const size_t bh = (size_t)(b*NHEAD + h);
    #pragma unroll
    for (int mi = 0; mi < 2; ++mi)
        #pragma unroll
        for (int half_ = 0; half_ < 2; ++half_){
            int rl = m0w + mi*16 + half_*8 + g;
            int s = sbase + rl;
            #pragma unroll
            for (int j = 0; j < 8; ++j){
                int d = n0w + j*8 + 2*t4;
                float v0 = acc[mi][j][half_*2]   + bias[n0 + d];
                float v1 = acc[mi][j][half_*2+1] + bias[n0 + d + 1];
                if (which == 0){
                    *(unsigned*)(g_Qh + (bh*SEQ + s)*Dh + d) = pack_h2(v0*QSCALE, v1*QSCALE);
                } else if (which == 1){
                    *(unsigned*)(g_Kh + (bh*SEQ + s)*Dh + d) = pack_h2(v0, v1);
                } else {
                    g_VTh[(bh*Dh + d)*SEQ + s]     = __float2half_rn(v0);
                    g_VTh[(bh*Dh + d + 1)*SEQ + s] = __float2half_rn(v1);
                }
            }
        }
}

// ---------------- fused attention (unchanged core) ----------------
__global__ __launch_bounds__(128, 2) void attn_mma(float* __restrict__ weights)
{
    extern __shared__ unsigned sm[];
    unsigned* Qs = sm;
    __shared__ float lpart[64][2];
    __shared__ float linvs[64];

    const int tid = threadIdx.x, lane = tid & 31, g = lane >> 2, t4 = lane & 3, w = tid >> 5;
    const int m0w = (w & 1) * 32;
    const int wn  = w >> 1;
    const int n0s = wn * 32;
    const int n0d = wn * 64;
    const int h = blockIdx.x, q0 = blockIdx.y * 64, b = blockIdx.z;
    const size_t bh = (size_t)(b*NHEAD + h);
    const __half* Qg  = g_Qh  + bh*SEQ*Dh + (size_t)q0*Dh;
    const __half* Kg  = g_Kh  + bh*SEQ*Dh;
    const __half* VTg = g_VTh + bh*SEQ*Dh;
    const unsigned* mbits = g_MBITS + (size_t)b*SEQ*(SEQ/32);
    float* wb = weights + bh*(size_t)SEQ*SEQ;

    const unsigned smb = smem_u32(sm);
    const unsigned kb_u[2] = { smb + OFF_KB0*4u, smb + OFF_KB1*4u };
    const unsigned vb_u[2] = { smb + OFF_VB0*4u, smb + OFF_VB1*4u };

    #pragma unroll
    for (int i = 0; i < 8; ++i){
        int idx = tid + i*128;
        int r = idx >> 4, c = idx & 15;
        cpa16(smb + (unsigned)(r*LQW + c*4)*4u, Qg + (size_t)r*Dh + c*8);
        cpa16(kb_u[0] + (unsigned)(r*LQW + c*4)*4u, Kg + (size_t)r*Dh + c*8);
        int rv = idx >> 3, cv = idx & 7;
        cpa16(vb_u[0] + (unsigned)(rv*LVW + cv*4)*4u, VTg + (size_t)rv*SEQ + cv*8);
    }
    asm volatile("cp.async.commit_group;");

    float lsum[2][2] = {{0.f,0.f},{0.f,0.f}};
    float ctx[2][8][4] = {};

    for (int it = 0; it < 32; ++it){
        const int t0 = it * 64;
        const int cur = it & 1, nxt = cur ^ 1;
        if (it + 1 < 32){
            const __half* Kn  = Kg  + (size_t)(t0 + 64)*Dh;
            const __half* VTn = VTg + (t0 + 64);
            #pragma unroll
            for (int i = 0; i < 8; ++i){
                int idx = tid + i*128;
                int r = idx >> 4, c = idx & 15;
                cpa16(kb_u[nxt] + (unsigned)(r*LQW + c*4)*4u, Kn + (size_t)r*Dh + c*8);
                int rv = idx >> 3, cv = idx & 7;
                cpa16(vb_u[nxt] + (unsigned)(rv*LVW + cv*4)*4u, VTn + (size_t)rv*SEQ + cv*8);
            }
            asm volatile("cp.async.commit_group;");
            asm volatile("cp.async.wait_group 1;");
        } else {
            asm volatile("cp.async.wait_group 0;");
        }
        __syncthreads();

        const unsigned* Ks = sm + (cur ? OFF_KB1 : OFF_KB0);
        const unsigned* Vs = sm + (cur ? OFF_VB1 : OFF_VB0);
        unsigned*       Ws = sm + (cur ? OFF_KB1 : OFF_KB0);

        float acc[2][4][4] = {};
        #pragma unroll
        for (int kk = 0; kk < 8; ++kk){
            unsigned a[2][4];
            #pragma unroll
            for (int mi = 0; mi < 2; ++mi){
                const unsigned* p = Qs + (m0w + mi*16 + g)*LQW + kk*8 + t4;
                a[mi][0] = p[0];       a[mi][2] = p[4];
                a[mi][1] = p[8*LQW];   a[mi][3] = p[8*LQW + 4];
            }
            #pragma unroll
            for (int j = 0; j < 4; ++j){
                const unsigned* p = Ks + (n0s + j*8 + g)*LQW + kk*8 + t4;
                mma16h(acc[0][j], a[0], p[0], p[4]);
                mma16h(acc[1][j], a[1], p[0], p[4]);
            }
        }
        __syncthreads();

        #pragma unroll
        for (int mi = 0; mi < 2; ++mi){
            const int rl0 = m0w + mi*16 + g;
            const int r0  = q0 + rl0;
            const int wword = (t0 + n0s) >> 5;
            const unsigned mb0 = mbits[(size_t)r0*(SEQ/32) + wword];
            const unsigned mb1 = mbits[(size_t)(r0+8)*(SEQ/32) + wword];
            float* wr0 = wb + (size_t)r0*SEQ + t0;
            float* wr1 = wr0 + 8*SEQ;
            #pragma unroll
            for (int j = 0; j < 4; ++j){
                int cc = n0s + j*8 + 2*t4;
                int sh = j*8 + 2*t4;
                float u00 = ((mb0 >> sh) & 1u)     ? 0.f : ex2f(acc[mi][j][0]);
                float u01 = ((mb0 >> (sh+1)) & 1u) ? 0.f : ex2f(acc[mi][j][1]);
                float u10 = ((mb1 >> sh) & 1u)     ? 0.f : ex2f(acc[mi][j][2]);
                float u11 = ((mb1 >> (sh+1)) & 1u) ? 0.f : ex2f(acc[mi][j][3]);
                *(float2*)(wr0 + cc) = make_float2(u00, u01);
                *(float2*)(wr1 + cc) = make_float2(u10, u11);
                lsum[mi][0] += u00 + u01;
                lsum[mi][1] += u10 + u11;
                Ws[rl0*LVW + (n0s >> 1) + 4*j + t4]       = pack_h2(u00, u01);
                Ws[(rl0 + 8)*LVW + (n0s >> 1) + 4*j + t4] = pack_h2(u10, u11);
            }
        }
        __syncthreads();

        #pragma unroll
        for (int kk = 0; kk < 4; ++kk){
            unsigned a[2][4];
            #pragma unroll
            for (int mi = 0; mi < 2; ++mi){
                const unsigned* p = Ws + (m0w + mi*16 + g)*LVW + kk*8 + t4;
                a[mi][0] = p[0];       a[mi][2] = p[4];
                a[mi][1] = p[8*LVW];   a[mi][3] = p[8*LVW + 4];
            }
            #pragma unroll
            for (int j = 0; j < 8; ++j){
                const unsigned* p = Vs + (n0d + j*8 + g)*LVW + kk*8 + t4;
                mma16h(ctx[0][j], a[0], p[0], p[4]);
                mma16h(ctx[1][j], a[1], p[0], p[4]);
            }
        }
        __syncthreads();
    }

    #pragma unroll
    for (int mi = 0; mi < 2; ++mi)
        #pragma unroll
        for (int half_ = 0; half_ < 2; ++half_){
            float v = lsum[mi][half_];
            v += __shfl_xor_sync(0xffffffffu, v, 1);
            v += __shfl_xor_sync(0xffffffffu, v, 2);
            if (t4 == 0) lpart[m0w + mi*16 + half_*8 + g][wn] = v;
        }
    __syncthreads();
    if (tid < 64){
        float li = 1.0f / (lpart[tid][0] + lpart[tid][1]);
        linvs[tid] = li;
        g_LINV[bh*SEQ + q0 + tid] = li;
    }
    __syncthreads();

    float* Cb = g_CTX + (bh*SEQ + (size_t)q0)*Dh;
    #pragma unroll
    for (int mi = 0; mi < 2; ++mi)
        #pragma unroll
        for (int half_ = 0; half_ < 2; ++half_){
            int rl = m0w + mi*16 + half_*8 + g;
            float li = linvs[rl];
            #pragma unroll
            for (int j = 0; j < 8; ++j){
                int d = n0d + j*8 + 2*t4;
                float c0 = __uint_as_float(f2tf32(ctx[mi][j][half_*2]*li));
                float c1 = __uint_as_float(f2tf32(ctx[mi][j][half_*2+1]*li));
                *(float2*)(Cb + (size_t)rl*Dh + d) = make_float2(c0, c1);
            }
        }
}

// ---------------- weights row-normalize (standalone, high-occupancy) ----------------
__global__ __launch_bounds__(256) void norm_w(float* __restrict__ weights)
{
    const float li = g_LINV[blockIdx.x];
    float4* row = (float4*)(weights + (size_t)blockIdx.x * SEQ);
    int t = threadIdx.x;
    float4 a = row[t], c = row[t + 256];
    a.x*=li; a.y*=li; a.z*=li; a.w*=li;
    c.x*=li; c.y*=li; c.z*=li; c.w*=li;
    row[t] = a; row[t + 256] = c;
}

// ---------------- output projection v2: 128 CTAs, cp.async double-buffered ----------
__global__ __launch_bounds__(256) void outproj_tc(const float* __restrict__ bd,
                                                  float* __restrict__ out)
{
    extern __shared__ unsigned sm[];
    const unsigned smb = smem_u32(sm);
    const int tid = threadIdx.x;
    const int lane = tid & 31, g = lane >> 2, t4 = lane & 3, w = tid >> 5;
    const int m0w = (w & 1) * 16, n0w = (w >> 1) * 32;
    const int m0 = blockIdx.x * 32;
    const int b = m0 >> 11, sbase = m0 & 2047;

    const unsigned oa[2] = { smb + OA0*4u, smb + OA1*4u };
    const unsigned ob[2] = { smb + OB0*4u, smb + OB1*4u };

    {
        const float* Ag = g_CTX + (((size_t)(b*NHEAD))*SEQ + sbase)*Dh;
        #pragma unroll
        for (int i = 0; i < 4; ++i){
            int idx = tid + i*256;
            int r = idx >> 5, c = (idx & 31) << 2;
            cpa16(oa[0] + (unsigned)(r*LDA + c)*4u, Ag + (size_t)r*Dh + c);
        }
        #pragma unroll
        for (int i = 0; i < 16; ++i){
            int idx = tid + i*256;
            int r = idx >> 5, c = (idx & 31) << 2;
            cpa16(ob[0] + (unsigned)(r*LDA + c)*4u, g_Wdr + (size_t)r*NHD + c);
        }
        asm volatile("cp.async.commit_group;");
    }

    float acc[4][4] = {};
    for (int kt = 0; kt < 16; ++kt){
        const int cur = kt & 1, nxt = cur ^ 1;
        if (kt + 1 < 16){
            const float* Ag = g_CTX + (((size_t)(b*NHEAD + kt + 1))*SEQ + sbase)*Dh;
            const float* Bg = g_Wdr + (kt + 1)*Dh;
            #pragma unroll
            for (int i = 0; i < 4; ++i){
                int idx = tid + i*256;
                int r = idx >> 5, c = (idx & 31) << 2;
                cpa16(oa[nxt] + (unsigned)(r*LDA + c)*4u, Ag + (size_t)r*Dh + c);
            }
            #pragma unroll
            for (int i = 0; i < 16; ++i){
                int idx = tid + i*256;
                int r = idx >> 5, c = (idx & 31) << 2;
                cpa16(ob[nxt] + (unsigned)(r*LDA + c)*4u, Bg + (size_t)r*NHD + c);
            }
            asm volatile("cp.async.commit_group;");
            asm volatile("cp.async.wait_group 1;");
        } else {
            asm volatile("cp.async.wait_group 0;");
        }
        __syncthreads();

        const unsigned* As = sm + (cur ? OA1 : OA0);
        const unsigned* Bs = sm + (cur ? OB1 : OB0);

        #pragma unroll 4
        for (int kk = 0; kk < 16; ++kk){
            unsigned a[4];
            const unsigned* pa = As + (m0w + g)*LDA + kk*8 + t4;
            a[0] = pa[0];       a[2] = pa[4];
            a[1] = pa[8*LDA];   a[3] = pa[8*LDA + 4];
            #pragma unroll
            for (int j = 0; j < 4; ++j){
                const unsigned* p = Bs + (n0w + j*8 + g)*LDA + kk*8 + t4;
                mma8(acc[j], a, p[0], p[4]);
            }
        }
        __syncthreads();
    }

    #pragma unroll
    for (int half_ = 0; half_ < 2; ++half_){
        int rl = m0w + half_*8 + g;
        float* Or = out + (size_t)(m0 + rl)*Dh;
        #pragma unroll
        for (int j = 0; j < 4; ++j){
            int d = n0w + j*8 + 2*t4;
            *(float2*)(Or + d) = make_float2(acc[j][half_*2]   + bd[d],
                                             acc[j][half_*2+1] + bd[d + 1]);
        }
    }
}

// ---------------------------------------------------------------------------
extern "C" void kernel_launch(void* const* d_in, const int* in_sizes, int n_in,
                              void* d_out, int out_size)
{
    (void)in_sizes; (void)n_in; (void)out_size;
    const float* x    = (const float*)d_in[0];
    const int*   mask = (const int*)  d_in[1];
    const float* Wq   = (const float*)d_in[2];
    const float* bq   = (const float*)d_in[3];
    const float* Wk   = (const float*)d_in[4];
    const float* bk   = (const float*)d_in[5];
    const float* Wv   = (const float*)d_in[6];
    const float* bv   = (const float*)d_in[7];
    const float* Wd   = (const float*)d_in[8];
    const float* bd   = (const float*)d_in[9];

    float* out     = (float*)d_out;
    float* weights = out + (size_t)NB*SEQ*Dh;

    const size_t smem_proj = (size_t)2*128*LDA*4;
    const size_t smem_attn = SMEM_ATTN;
    const size_t smem_op   = SMEM_OP;

    cudaFuncSetAttribute(stage1,     cudaFuncAttributeMaxDynamicSharedMemorySize, (int)smem_proj);
    cudaFuncSetAttribute(attn_mma,   cudaFuncAttributeMaxDynamicSharedMemorySize, (int)smem_attn);
    cudaFuncSetAttribute(outproj_tc, cudaFuncAttributeMaxDynamicSharedMemorySize, (int)smem_op);

    dim3 g1(NHD/128, MROWS/128, 4);
    stage1<<<g1, 256, smem_proj>>>(x, mask, Wq, bq, Wk, bk, Wv, bv, Wd);

    dim3 g2(NHEAD, SEQ/64, NB);
    attn_mma<<<g2, 128, smem_attn>>>(weights);

    norm_w<<<NB*NHEAD*SEQ, 256>>>(weights);

    outproj_tc<<<MROWS/32, 256, smem_op>>>(bd, out);
}

// round 17
// speedup vs baseline: 1.1708x; 1.0233x over previous
#include <cuda_runtime.h>
#include <cuda_fp16.h>

#define Dh 128
#define NHEAD 16
#define NB 2
#define SEQ 2048
#define NHD (NHEAD*Dh)
#define MROWS (NB*SEQ)

__device__ __half g_Qh[(size_t)NB*NHEAD*SEQ*Dh];
__device__ __half g_Kh[(size_t)NB*NHEAD*SEQ*Dh];
__device__ __half g_VTh[(size_t)NB*NHEAD*SEQ*Dh];
__device__ float  g_CTX[(size_t)NB*NHEAD*SEQ*Dh];   // tf32-pre-rounded
__device__ float  g_Wdr[(size_t)Dh*NHD];            // Wd tf32-pre-rounded
__device__ float  g_LINV[(size_t)NB*NHEAD*SEQ];
__device__ unsigned g_MBITS[(size_t)NB*SEQ*(SEQ/32)];

#define LDA 132
#define LQW 68
#define LVW 36
// attn smem (words): [0,4352) Q staging -> w tile; then K0,K1,V0,V1
#define OFF_KB0 4352
#define OFF_KB1 (4352 + 4352)
#define OFF_VB0 (4352 + 2*4352)
#define OFF_VB1 (4352 + 2*4352 + 4608)
#define SMEM_ATTN ((4352 + 2*4352 + 2*4608) * 4)    // 89088 B

#define OA0 0
#define OA1 4224
#define OB0 8448
#define OB1 25344
#define SMEM_OP (42240 * 4)

#define QSCALE 0.12751744532f

__device__ __forceinline__ unsigned f2tf32(float f){
    unsigned r; asm("cvt.rna.tf32.f32 %0, %1;" : "=r"(r) : "f"(f)); return r;
}
__device__ __forceinline__ float ex2f(float x){
    float r; asm("ex2.approx.f32 %0, %1;" : "=f"(r) : "f"(x)); return r;
}
__device__ __forceinline__ unsigned pack_h2(float a, float b){
    unsigned r; asm("cvt.rn.f16x2.f32 %0, %2, %1;" : "=r"(r) : "f"(a), "f"(b)); return r;
}
__device__ __forceinline__ void mma8(float* d, const unsigned* a, unsigned b0, unsigned b1){
    asm volatile("mma.sync.aligned.m16n8k8.row.col.f32.tf32.tf32.f32 "
        "{%0,%1,%2,%3},{%4,%5,%6,%7},{%8,%9},{%0,%1,%2,%3};"
        : "+f"(d[0]), "+f"(d[1]), "+f"(d[2]), "+f"(d[3])
        : "r"(a[0]), "r"(a[1]), "r"(a[2]), "r"(a[3]), "r"(b0), "r"(b1));
}
__device__ __forceinline__ void mma16h(float* d, const unsigned* a, unsigned b0, unsigned b1){
    asm volatile("mma.sync.aligned.m16n8k16.row.col.f32.f16.f16.f32 "
        "{%0,%1,%2,%3},{%4,%5,%6,%7},{%8,%9},{%0,%1,%2,%3};"
        : "+f"(d[0]), "+f"(d[1]), "+f"(d[2]), "+f"(d[3])
        : "r"(a[0]), "r"(a[1]), "r"(a[2]), "r"(a[3]), "r"(b0), "r"(b1));
}
__device__ __forceinline__ unsigned smem_u32(const void* p){
    unsigned a;
    asm("{ .reg .u64 t; cvta.to.shared.u64 t, %1; cvt.u32.u64 %0, t; }" : "=r"(a) : "l"(p));
    return a;
}
__device__ __forceinline__ void cpa16(unsigned s, const void* g){
    asm volatile("cp.async.ca.shared.global [%0], [%1], 16;" :: "r"(s), "l"(g));
}

template<int NT, int ROWS>
__device__ __forceinline__ void load_tile(unsigned* dst, const float* src, int srcStride,
                                          int tid){
    #pragma unroll
    for (int it = 0; it < ROWS*32/NT; ++it){
        int idx = tid + it*NT;
        int r = idx >> 5, c = (idx & 31) << 2;
        float4 v = *(const float4*)(src + (size_t)r*srcStride + c);
        uint4 u = make_uint4(f2tf32(v.x), f2tf32(v.y), f2tf32(v.z), f2tf32(v.w));
        *(uint4*)(dst + r*LDA + c) = u;
    }
}

// ---------------- stage 1: QKV proj (z=0..2) + mask bitpack / Wd round (z=3) ----------
__global__ __launch_bounds__(256) void stage1(
    const float* __restrict__ X, const int* __restrict__ mask,
    const float* __restrict__ Wq, const float* __restrict__ bq,
    const float* __restrict__ Wk, const float* __restrict__ bk,
    const float* __restrict__ Wv, const float* __restrict__ bv,
    const float* __restrict__ Wd)
{
    const int tid = threadIdx.x;
    const int which = blockIdx.z;

    if (which == 3){
        size_t p = (size_t)blockIdx.y * 16 + blockIdx.x;
        #pragma unroll
        for (int k = 0; k < 2; ++k){
            size_t o = p*512 + tid*2 + k;
            const int* src = mask + o*32;
            unsigned bits = 0;
            #pragma unroll
            for (int i = 0; i < 32; i += 4){
                int4 v = *(const int4*)(src + i);
                bits |= ((unsigned)(v.x & 1) << i)     | ((unsigned)(v.y & 1) << (i+1))
                      | ((unsigned)(v.z & 1) << (i+2)) | ((unsigned)(v.w & 1) << (i+3));
            }
            g_MBITS[o] = bits;
        }
        {
            size_t base = p * 512;
            if (tid < 128){
                float4 v = *(const float4*)(Wd + base + tid*4);
                uint4 u = make_uint4(f2tf32(v.x), f2tf32(v.y), f2tf32(v.z), f2tf32(v.w));
                *(uint4*)(g_Wdr + base + tid*4) = u;
            }
        }
        return;
    }

    extern __shared__ unsigned sm[];
    unsigned* As = sm;
    unsigned* Bs = sm + 128*LDA;
    const int lane = tid & 31, g = lane >> 2, t4 = lane & 3, w = tid >> 5;
    const int m0w = (w & 3) * 32, n0w = (w >> 2) * 64;
    const int m0 = blockIdx.y * 128, n0 = blockIdx.x * 128;

    const float* W    = (which == 0) ? Wq : (which == 1) ? Wk : Wv;
    const float* bias = (which == 0) ? bq : (which == 1) ? bk : bv;

    load_tile<256,128>(As, X + (size_t)m0*Dh, Dh, tid);
    load_tile<256,128>(Bs, W + (size_t)n0*Dh, Dh, tid);
    __syncthreads();

    float acc[2][8][4] = {};
    #pragma unroll 4
    for (int kk = 0; kk < 16; ++kk){
        unsigned a[2][4];
        #pragma unroll
        for (int mi = 0; mi < 2; ++mi){
            const unsigned* p = As + (m0w + mi*16 + g)*LDA + kk*8 + t4;
            a[mi][0] = p[0];       a[mi][2] = p[4];
            a[mi][1] = p[8*LDA];   a[mi][3] = p[8*LDA + 4];
        }
        #pragma unroll
        for (int j = 0; j < 8; ++j){
            const unsigned* p = Bs + (n0w + j*8 + g)*LDA + kk*8 + t4;
            mma8(acc[0][j], a[0], p[0], p[4]);
            mma8(acc[1][j], a[1], p[0], p[4]);
        }
    }

    const int b = m0 >> 11, sbase = m0 & 2047, h = n0 >> 7;
    const size_t bh = (size_t)(b*NHEAD + h);
    #pragma unroll
    for (int mi = 0; mi < 2; ++mi)
        #pragma unroll
        for (int half_ = 0; half_ < 2; ++half_){
            int rl = m0w + mi*16 + half_*8 + g;
            int s = sbase + rl;
            #pragma unroll
            for (int j = 0; j < 8; ++j){
                int d = n0w + j*8 + 2*t4;
                float v0 = acc[mi][j][half_*2]   + bias[n0 + d];
                float v1 = acc[mi][j][half_*2+1] + bias[n0 + d + 1];
                if (which == 0){
                    *(unsigned*)(g_Qh + (bh*SEQ + s)*Dh + d) = pack_h2(v0*QSCALE, v1*QSCALE);
                } else if (which == 1){
                    *(unsigned*)(g_Kh + (bh*SEQ + s)*Dh + d) = pack_h2(v0, v1);
                } else {
                    g_VTh[(bh*Dh + d)*SEQ + s]     = __float2half_rn(v0);
                    g_VTh[(bh*Dh + d + 1)*SEQ + s] = __float2half_rn(v1);
                }
            }
        }
}

// ---------------- fused attention v2: Q in registers, 2 barriers/iter ----------------
__global__ __launch_bounds__(128, 2) void attn_mma(float* __restrict__ weights)
{
    extern __shared__ unsigned sm[];
    __shared__ float lpart[64][2];
    __shared__ float linvs[64];

    const int tid = threadIdx.x, lane = tid & 31, g = lane >> 2, t4 = lane & 3, w = tid >> 5;
    const int m0w = (w & 1) * 32;
    const int wn  = w >> 1;
    const int n0s = wn * 32;
    const int n0d = wn * 64;
    const int h = blockIdx.x, q0 = blockIdx.y * 64, b = blockIdx.z;
    const size_t bh = (size_t)(b*NHEAD + h);
    const __half* Qg  = g_Qh  + bh*SEQ*Dh + (size_t)q0*Dh;
    const __half* Kg  = g_Kh  + bh*SEQ*Dh;
    const __half* VTg = g_VTh + bh*SEQ*Dh;
    const unsigned* mbits = g_MBITS + (size_t)b*SEQ*(SEQ/32);
    float* wb = weights + bh*(size_t)SEQ*SEQ;

    const unsigned smb = smem_u32(sm);
    const unsigned kb_u[2] = { smb + OFF_KB0*4u, smb + OFF_KB1*4u };
    const unsigned vb_u[2] = { smb + OFF_VB0*4u, smb + OFF_VB1*4u };
    unsigned* Qs = sm;              // staging; becomes w tile after it==0 fragment read
    unsigned* Ws = sm;

    // prologue: Q (staging) + K0 + V0
    #pragma unroll
    for (int i = 0; i < 8; ++i){
        int idx = tid + i*128;
        int r = idx >> 4, c = idx & 15;
        cpa16(smb + (unsigned)(r*LQW + c*4)*4u, Qg + (size_t)r*Dh + c*8);
        cpa16(kb_u[0] + (unsigned)(r*LQW + c*4)*4u, Kg + (size_t)r*Dh + c*8);
        int rv = idx >> 3, cv = idx & 7;
        cpa16(vb_u[0] + (unsigned)(rv*LVW + cv*4)*4u, VTg + (size_t)rv*SEQ + cv*8);
    }
    asm volatile("cp.async.commit_group;");

    unsigned qf[8][2][4];           // Q fragments, loop-invariant
    float lsum[2][2] = {{0.f,0.f},{0.f,0.f}};
    float ctx[2][8][4] = {};

    for (int it = 0; it < 32; ++it){
        const int t0 = it * 64;
        const int cur = it & 1, nxt = cur ^ 1;

        asm volatile("cp.async.wait_group 0;");
        __syncthreads();            // cur K/V ready; all warps done with prev iter

        if (it == 0){
            #pragma unroll
            for (int kk = 0; kk < 8; ++kk)
                #pragma unroll
                for (int mi = 0; mi < 2; ++mi){
                    const unsigned* p = Qs + (m0w + mi*16 + g)*LQW + kk*8 + t4;
                    qf[kk][mi][0] = p[0];       qf[kk][mi][2] = p[4];
                    qf[kk][mi][1] = p[8*LQW];   qf[kk][mi][3] = p[8*LQW + 4];
                }
            __syncthreads();        // all Q reads done before Ws writes
        }

        // prefetch next K/V (safe: everyone past prev iter's PV of buffer nxt)
        if (it + 1 < 32){
            const __half* Kn  = Kg  + (size_t)(t0 + 64)*Dh;
            const __half* VTn = VTg + (t0 + 64);
            #pragma unroll
            for (int i = 0; i < 8; ++i){
                int idx = tid + i*128;
                int r = idx >> 4, c = idx & 15;
                cpa16(kb_u[nxt] + (unsigned)(r*LQW + c*4)*4u, Kn + (size_t)r*Dh + c*8);
                int rv = idx >> 3, cv = idx & 7;
                cpa16(vb_u[nxt] + (unsigned)(rv*LVW + cv*4)*4u, VTn + (size_t)rv*SEQ + cv*8);
            }
            asm volatile("cp.async.commit_group;");
        }

        const unsigned* Ks = sm + (cur ? OFF_KB1 : OFF_KB0);
        const unsigned* Vs = sm + (cur ? OFF_VB1 : OFF_VB0);

        // ---- QK: fp16 k16, Q fragments from registers ----
        float acc[2][4][4] = {};
        #pragma unroll
        for (int kk = 0; kk < 8; ++kk){
            #pragma unroll
            for (int j = 0; j < 4; ++j){
                const unsigned* p = Ks + (n0s + j*8 + g)*LQW + kk*8 + t4;
                unsigned b0 = p[0], b1 = p[4];
                mma16h(acc[0][j], qf[kk][0], b0, b1);
                mma16h(acc[1][j], qf[kk][1], b0, b1);
            }
        }

        // ---- epilogue: u = masked ? 0 : ex2(s); STG u; STS u (own rows/cols) ----
        #pragma unroll
        for (int mi = 0; mi < 2; ++mi){
            const int rl0 = m0w + mi*16 + g;
            const int r0  = q0 + rl0;
            const int wword = (t0 + n0s) >> 5;
            const unsigned mb0 = mbits[(size_t)r0*(SEQ/32) + wword];
            const unsigned mb1 = mbits[(size_t)(r0+8)*(SEQ/32) + wword];
            float* wr0 = wb + (size_t)r0*SEQ + t0;
            float* wr1 = wr0 + 8*SEQ;
            #pragma unroll
            for (int j = 0; j < 4; ++j){
                int cc = n0s + j*8 + 2*t4;
                int sh = j*8 + 2*t4;
                float u00 = ((mb0 >> sh) & 1u)     ? 0.f : ex2f(acc[mi][j][0]);
                float u01 = ((mb0 >> (sh+1)) & 1u) ? 0.f : ex2f(acc[mi][j][1]);
                float u10 = ((mb1 >> sh) & 1u)     ? 0.f : ex2f(acc[mi][j][2]);
                float u11 = ((mb1 >> (sh+1)) & 1u) ? 0.f : ex2f(acc[mi][j][3]);
                *(float2*)(wr0 + cc) = make_float2(u00, u01);
                *(float2*)(wr1 + cc) = make_float2(u10, u11);
                lsum[mi][0] += u00 + u01;
                lsum[mi][1] += u10 + u11;
                Ws[rl0*LVW + (n0s >> 1) + 4*j + t4]       = pack_h2(u00, u01);
                Ws[(rl0 + 8)*LVW + (n0s >> 1) + 4*j + t4] = pack_h2(u10, u11);
            }
        }
        __syncthreads();            // w tile complete (V already resident)

        // ---- PV: ctx += w(64x64) * V(64x128) ----
        #pragma unroll
        for (int kk = 0; kk < 4; ++kk){
            unsigned a[2][4];
            #pragma unroll
            for (int mi = 0; mi < 2; ++mi){
                const unsigned* p = Ws + (m0w + mi*16 + g)*LVW + kk*8 + t4;
                a[mi][0] = p[0];       a[mi][2] = p[4];
                a[mi][1] = p[8*LVW];   a[mi][3] = p[8*LVW + 4];
            }
            #pragma unroll
            for (int j = 0; j < 8; ++j){
                const unsigned* p = Vs + (n0d + j*8 + g)*LVW + kk*8 + t4;
                mma16h(ctx[0][j], a[0], p[0], p[4]);
                mma16h(ctx[1][j], a[1], p[0], p[4]);
            }
        }
        // no trailing barrier: next iter's entry sync covers buffer reuse
    }

    #pragma unroll
    for (int mi = 0; mi < 2; ++mi)
        #pragma unroll
        for (int half_ = 0; half_ < 2; ++half_){
            float v = lsum[mi][half_];
            v += __shfl_xor_sync(0xffffffffu, v, 1);
            v += __shfl_xor_sync(0xffffffffu, v, 2);
            if (t4 == 0) lpart[m0w + mi*16 + half_*8 + g][wn] = v;
        }
    __syncthreads();
    if (tid < 64){
        float li = 1.0f / (lpart[tid][0] + lpart[tid][1]);
        linvs[tid] = li;
        g_LINV[bh*SEQ + q0 + tid] = li;
    }
    __syncthreads();

    float* Cb = g_CTX + (bh*SEQ + (size_t)q0)*Dh;
    #pragma unroll
    for (int mi = 0; mi < 2; ++mi)
        #pragma unroll
        for (int half_ = 0; half_ < 2; ++half_){
            int rl = m0w + mi*16 + half_*8 + g;
            float li = linvs[rl];
            #pragma unroll
            for (int j = 0; j < 8; ++j){
                int d = n0d + j*8 + 2*t4;
                float c0 = __uint_as_float(f2tf32(ctx[mi][j][half_*2]*li));
                float c1 = __uint_as_float(f2tf32(ctx[mi][j][half_*2+1]*li));
                *(float2*)(Cb + (size_t)rl*Dh + d) = make_float2(c0, c1);
            }
        }
}

// ---------------- weights row-normalize ----------------
__global__ __launch_bounds__(256) void norm_w(float* __restrict__ weights)
{
    const float li = g_LINV[blockIdx.x];
    float4* row = (float4*)(weights + (size_t)blockIdx.x * SEQ);
    int t = threadIdx.x;
    float4 a = row[t], c = row[t + 256];
    a.x*=li; a.y*=li; a.z*=li; a.w*=li;
    c.x*=li; c.y*=li; c.z*=li; c.w*=li;
    row[t] = a; row[t + 256] = c;
}

// ---------------- output projection v2 (unchanged from R13) ----------------
__global__ __launch_bounds__(256) void outproj_tc(const float* __restrict__ bd,
                                                  float* __restrict__ out)
{
    extern __shared__ unsigned sm[];
    const unsigned smb = smem_u32(sm);
    const int tid = threadIdx.x;
    const int lane = tid & 31, g = lane >> 2, t4 = lane & 3, w = tid >> 5;
    const int m0w = (w & 1) * 16, n0w = (w >> 1) * 32;
    const int m0 = blockIdx.x * 32;
    const int b = m0 >> 11, sbase = m0 & 2047;

    const unsigned oa[2] = { smb + OA0*4u, smb + OA1*4u };
    const unsigned ob[2] = { smb + OB0*4u, smb + OB1*4u };

    {
        const float* Ag = g_CTX + (((size_t)(b*NHEAD))*SEQ + sbase)*Dh;
        #pragma unroll
        for (int i = 0; i < 4; ++i){
            int idx = tid + i*256;
            int r = idx >> 5, c = (idx & 31) << 2;
            cpa16(oa[0] + (unsigned)(r*LDA + c)*4u, Ag + (size_t)r*Dh + c);
        }
        #pragma unroll
        for (int i = 0; i < 16; ++i){
            int idx = tid + i*256;
            int r = idx >> 5, c = (idx & 31) << 2;
            cpa16(ob[0] + (unsigned)(r*LDA + c)*4u, g_Wdr + (size_t)r*NHD + c);
        }
        asm volatile("cp.async.commit_group;");
    }

    float acc[4][4] = {};
    for (int kt = 0; kt < 16; ++kt){
        const int cur = kt & 1, nxt = cur ^ 1;
        if (kt + 1 < 16){
            const float* Ag = g_CTX + (((size_t)(b*NHEAD + kt + 1))*SEQ + sbase)*Dh;
            const float* Bg = g_Wdr + (kt + 1)*Dh;
            #pragma unroll
            for (int i = 0; i < 4; ++i){
                int idx = tid + i*256;
                int r = idx >> 5, c = (idx & 31) << 2;
                cpa16(oa[nxt] + (unsigned)(r*LDA + c)*4u, Ag + (size_t)r*Dh + c);
            }
            #pragma unroll
            for (int i = 0; i < 16; ++i){
                int idx = tid + i*256;
                int r = idx >> 5, c = (idx & 31) << 2;
                cpa16(ob[nxt] + (unsigned)(r*LDA + c)*4u, Bg + (size_t)r*NHD + c);
            }
            asm volatile("cp.async.commit_group;");
            asm volatile("cp.async.wait_group 1;");
        } else {
            asm volatile("cp.async.wait_group 0;");
        }
        __syncthreads();

        const unsigned* As = sm + (cur ? OA1 : OA0);
        const unsigned* Bs = sm + (cur ? OB1 : OB0);

        #pragma unroll 4
        for (int kk = 0; kk < 16; ++kk){
            unsigned a[4];
            const unsigned* pa = As + (m0w + g)*LDA + kk*8 + t4;
            a[0] = pa[0];       a[2] = pa[4];
            a[1] = pa[8*LDA];   a[3] = pa[8*LDA + 4];
            #pragma unroll
            for (int j = 0; j < 4; ++j){
                const unsigned* p = Bs + (n0w + j*8 + g)*LDA + kk*8 + t4;
                mma8(acc[j], a, p[0], p[4]);
            }
        }
        __syncthreads();
    }

    #pragma unroll
    for (int half_ = 0; half_ < 2; ++half_){
        int rl = m0w + half_*8 + g;
        float* Or = out + (size_t)(m0 + rl)*Dh;
        #pragma unroll
        for (int j = 0; j < 4; ++j){
            int d = n0w + j*8 + 2*t4;
            *(float2*)(Or + d) = make_float2(acc[j][half_*2]   + bd[d],
                                             acc[j][half_*2+1] + bd[d + 1]);
        }
    }
}

// ---------------------------------------------------------------------------
extern "C" void kernel_launch(void* const* d_in, const int* in_sizes, int n_in,
                              void* d_out, int out_size)
{
    (void)in_sizes; (void)n_in; (void)out_size;
    const float* x    = (const float*)d_in[0];
    const int*   mask = (const int*)  d_in[1];
    const float* Wq   = (const float*)d_in[2];
    const float* bq   = (const float*)d_in[3];
    const float* Wk   = (const float*)d_in[4];
    const float* bk   = (const float*)d_in[5];
    const float* Wv   = (const float*)d_in[6];
    const float* bv   = (const float*)d_in[7];
    const float* Wd   = (const float*)d_in[8];
    const float* bd   = (const float*)d_in[9];

    float* out     = (float*)d_out;
    float* weights = out + (size_t)NB*SEQ*Dh;

    const size_t smem_proj = (size_t)2*128*LDA*4;
    const size_t smem_attn = SMEM_ATTN;
    const size_t smem_op   = SMEM_OP;

    cudaFuncSetAttribute(stage1,     cudaFuncAttributeMaxDynamicSharedMemorySize, (int)smem_proj);
    cudaFuncSetAttribute(attn_mma,   cudaFuncAttributeMaxDynamicSharedMemorySize, (int)smem_attn);
    cudaFuncSetAttribute(outproj_tc, cudaFuncAttributeMaxDynamicSharedMemorySize, (int)smem_op);

    dim3 g1(NHD/128, MROWS/128, 4);
    stage1<<<g1, 256, smem_proj>>>(x, mask, Wq, bq, Wk, bk, Wv, bv, Wd);

    dim3 g2(NHEAD, SEQ/64, NB);
    attn_mma<<<g2, 128, smem_attn>>>(weights);

    norm_w<<<NB*NHEAD*SEQ, 256>>>(weights);

    outproj_tc<<<MROWS/32, 256, smem_op>>>(bd, out);
}